// round 1
// baseline (speedup 1.0000x reference)
#include <cuda_runtime.h>
#include <stdint.h>

// Problem constants (from reference): B=4096 rows, P=8192 cols.
#define ROW_P    8192
#define NBKT     4096
#define NTHREADS 1024

// Dynamic smem layout:
//   s_pair : ROW_P  x u64   (packed (flipped_key<<16)|col_idx, scattered by bucket)
//   s_base : NBKT+1 x u32   (exclusive scan of bucket counts; [NBKT] = total negatives)
//   s_off  : NBKT   x u32   (counts, then running scatter offsets)
#define SMEM_BYTES (ROW_P * 8 + (NBKT + 1) * 4 + NBKT * 4)

extern __shared__ unsigned char smem_raw[];

__global__ __launch_bounds__(NTHREADS, 2)
void qp_rank_kernel(const float* __restrict__ x,
                    const float* __restrict__ rho,
                    const float* __restrict__ c,
                    float* __restrict__ out)
{
    unsigned long long* s_pair = (unsigned long long*)smem_raw;
    uint32_t* s_base = (uint32_t*)(smem_raw + ROW_P * 8);
    uint32_t* s_off  = s_base + (NBKT + 1);
    __shared__ uint32_t wsum[32];

    const int t   = threadIdx.x;
    const int row = blockIdx.x;
    const float* __restrict__ xr = x   + (size_t)row * ROW_P;
    const float* __restrict__ rr = rho + (size_t)row * ROW_P;
    float* __restrict__ outr     = out + (size_t)row * ROW_P;

    // ---- zero bucket counters ----
    #pragma unroll
    for (int i = t; i < NBKT; i += NTHREADS) s_off[i] = 0;
    __syncthreads();

    // ---- phase 1: classify. Positives (key >= 0) are done immediately:
    //      max(x, -c) = x since x >= 0 >= -c.  Negatives get histogrammed. ----
    #pragma unroll
    for (int k = 0; k < ROW_P / NTHREADS; ++k) {
        int j = t + k * NTHREADS;
        float xv = xr[j];
        float kf = xv * rr[j];
        if (kf < 0.0f) {
            uint32_t u = ~__float_as_uint(kf);   // monotone ascending for negatives, bit31=0
            atomicAdd(&s_off[u >> 19], 1u);      // 12-bit bucket: 8 exp + 4 mantissa bits
        } else {
            outr[j] = xv;
        }
    }
    __syncthreads();

    // ---- exclusive block scan of 4096 counts -> s_base, s_base[NBKT] = total ----
    {
        const int lane = t & 31, warp = t >> 5;
        uint32_t c0 = s_off[4*t+0], c1 = s_off[4*t+1], c2 = s_off[4*t+2], c3 = s_off[4*t+3];
        uint32_t p1 = c0 + c1;
        uint32_t p2 = p1 + c2;
        uint32_t tsum = p2 + c3;
        uint32_t s = tsum;
        #pragma unroll
        for (int d = 1; d < 32; d <<= 1) {
            uint32_t v = __shfl_up_sync(0xFFFFFFFFu, s, d);
            if (lane >= d) s += v;
        }
        if (lane == 31) wsum[warp] = s;
        __syncthreads();
        if (warp == 0) {
            uint32_t ws = wsum[lane];
            uint32_t sc = ws;
            #pragma unroll
            for (int d = 1; d < 32; d <<= 1) {
                uint32_t v = __shfl_up_sync(0xFFFFFFFFu, sc, d);
                if (lane >= d) sc += v;
            }
            wsum[lane] = sc - ws;   // exclusive warp offsets
        }
        __syncthreads();
        uint32_t ex = wsum[warp] + (s - tsum);   // exclusive prefix for this thread's 4 buckets
        s_base[4*t+0] = ex;
        s_base[4*t+1] = ex + c0;
        s_base[4*t+2] = ex + p1;
        s_base[4*t+3] = ex + p2;
        if (t == NTHREADS - 1) s_base[NBKT] = ex + tsum;
    }
    __syncthreads();

    // ---- copy base -> running offsets ----
    #pragma unroll
    for (int i = t; i < NBKT; i += NTHREADS) s_off[i] = s_base[i];
    __syncthreads();

    // ---- phase 2: scatter negatives into bucket-contiguous slots ----
    #pragma unroll
    for (int k = 0; k < ROW_P / NTHREADS; ++k) {
        int j = t + k * NTHREADS;
        float kf = xr[j] * rr[j];   // re-read: row still in L2
        if (kf < 0.0f) {
            uint32_t u = ~__float_as_uint(kf);
            uint32_t p = atomicAdd(&s_off[u >> 19], 1u);
            s_pair[p] = ((unsigned long long)u << 16) | (unsigned)j;
        }
    }
    __syncthreads();

    // ---- phase 3: exact stable rank within bucket (u64 compare = key, then idx),
    //      then out[j] = max(x[j], -c[rank]). Warp lanes share a bucket ->
    //      s_pair[q] loads are broadcast. ----
    const int n = (int)s_base[NBKT];
    for (int p = t; p < n; p += NTHREADS) {
        unsigned long long me = s_pair[p];
        uint32_t u = (uint32_t)(me >> 16);
        uint32_t b = u >> 19;
        int lo = (int)s_base[b];
        int hi = (int)s_base[b + 1];
        int rank = lo;
        for (int q = lo; q < hi; ++q) {
            rank += (s_pair[q] < me) ? 1 : 0;
        }
        int j = (int)(me & 0xFFFFu);
        float xv = __ldg(&xr[j]);
        outr[j] = fmaxf(xv, -__ldg(&c[rank]));
    }
}

extern "C" void kernel_launch(void* const* d_in, const int* in_sizes, int n_in,
                              void* d_out, int out_size)
{
    const float* x   = (const float*)d_in[0];
    const float* rho = (const float*)d_in[1];
    const float* c   = (const float*)d_in[2];
    float* out = (float*)d_out;

    const int B = in_sizes[0] / ROW_P;   // 4096

    cudaFuncSetAttribute(qp_rank_kernel,
                         cudaFuncAttributeMaxDynamicSharedMemorySize, SMEM_BYTES);
    qp_rank_kernel<<<B, NTHREADS, SMEM_BYTES>>>(x, rho, c, out);
}